// round 5
// baseline (speedup 1.0000x reference)
#include <cuda_runtime.h>
#include <math.h>

#define N_DOC 10000
#define N_WORD 20000
#define N_ENT 10000
#define N_POS 60
#define DIM 128
#define D_POS_IN 60
#define D_WEMB 300
#define E11 320000
#define E22 160000
#define E33 3600
#define E01 300000
#define E02 100000
#define E03 150000

typedef unsigned long long ull;

// merged offsets (compile time)
enum { CU11 = 0, CU22 = 20000, CU33 = 30000, CU01 = 30060, CU02 = 40060, CU03 = 50060, CU_TOT = 60060 };
enum { RP11 = 0, RP22 = 20001, RP33 = 30002, RP01 = 30063, RP02 = 40064, RP03 = 50065, RP_TOT = 60066 };
enum { EO11 = 0, EO22 = 320000, EO33 = 480000, EO01 = 483600, EO02 = 783600, EO03 = 883600, E_TOT = 1033600 };

// hist & scatter: 4 edges/thread (1024 edges/block)
enum { H11 = 313, H22 = 470, H33 = 474, H01 = 767, H02 = 865, H03 = 1012 };

// ---------------- scratch ----------------
__device__ int   g_cu[CU_TOT];
__device__ int   g_rp[RP_TOT];
__device__ int   g_cols[E_TOT];
__device__ float g_vals[E_TOT];

__device__ float g_t1[N_WORD * DIM];
__device__ float g_h1[N_WORD * DIM];
__device__ float g_t2[N_ENT * DIM];
__device__ float g_h2[N_ENT * DIM];
__device__ float g_t3a[N_POS * DIM];
__device__ float g_h3[N_POS * DIM];

// ---------------- packed fp32 helpers ----------------
__device__ __forceinline__ ull fma2(ull a, ull b, ull c) {
    ull d;
    asm("fma.rn.f32x2 %0, %1, %2, %3;" : "=l"(d) : "l"(a), "l"(b), "l"(c));
    return d;
}
__device__ __forceinline__ ull pack2(float lo, float hi) {
    ull d;
    asm("mov.b64 %0, {%1, %2};" : "=l"(d) : "f"(lo), "f"(hi));
    return d;
}
__device__ __forceinline__ float2 unpack2(ull v) {
    float2 r;
    asm("mov.b64 {%0, %1}, %2;" : "=f"(r.x), "=f"(r.y) : "l"(v));
    return r;
}

// ---------------- CSR build ----------------
__global__ void k_zero() {
    int i = blockIdx.x * blockDim.x + threadIdx.x;
    if (i < CU_TOT) g_cu[i] = 0;
}

__global__ void k_hist_all(const int* __restrict__ r11, const int* __restrict__ r22,
                           const int* __restrict__ r33, const int* __restrict__ r01,
                           const int* __restrict__ r02, const int* __restrict__ r03) {
    int b = blockIdx.x, t = threadIdx.x;
    const int* rows; int E, off, b0;
    if (b < H11)      { rows = r11; E = E11; off = CU11; b0 = 0; }
    else if (b < H22) { rows = r22; E = E22; off = CU22; b0 = H11; }
    else if (b < H33) { rows = r33; E = E33; off = CU33; b0 = H22; }
    else if (b < H01) { rows = r01; E = E01; off = CU01; b0 = H33; }
    else if (b < H02) { rows = r02; E = E02; off = CU02; b0 = H01; }
    else              { rows = r03; E = E03; off = CU03; b0 = H02; }
    int e0 = (b - b0) * 1024 + t;
#pragma unroll
    for (int j = 0; j < 4; j++) {
        int e = e0 + j * 256;
        if (e < E) atomicAdd(&g_cu[off + rows[e]], 1);
    }
}

__global__ void k_scan_all() {
    __shared__ int wsum[32];
    const int ns[6]  = {N_WORD, N_ENT, N_POS, N_DOC, N_DOC, N_DOC};
    const int cuo[6] = {CU11, CU22, CU33, CU01, CU02, CU03};
    const int rpo[6] = {RP11, RP22, RP33, RP01, RP02, RP03};
    int g = blockIdx.x;
    int n = ns[g];
    int* cnt = g_cu + cuo[g];
    int* rp  = g_rp + rpo[g];
    int tid = threadIdx.x;  // 1024
    int chunk = (n + 1023) >> 10;
    int base = tid * chunk;
    int end = base + chunk; if (end > n) end = n;
    int s = 0;
    for (int i = base; i < end && i >= base; i++) s += cnt[i];
    int lane = tid & 31, w = tid >> 5;
    int v = s;
#pragma unroll
    for (int o = 1; o < 32; o <<= 1) { int u = __shfl_up_sync(~0u, v, o); if (lane >= o) v += u; }
    if (lane == 31) wsum[w] = v;
    __syncthreads();
    if (w == 0) {
        int x = wsum[lane];
#pragma unroll
        for (int o = 1; o < 32; o <<= 1) { int u = __shfl_up_sync(~0u, x, o); if (lane >= o) x += u; }
        wsum[lane] = x;
    }
    __syncthreads();
    int excl = v - s + (w > 0 ? wsum[w - 1] : 0);
    int run = excl;
    for (int i = base; i < end && i >= base; i++) {
        int c = cnt[i];
        cnt[i] = run;
        rp[i] = run;
        run += c;
    }
    if (end == n || base >= n) rp[n] = run;
}

__global__ void k_scatter_all(const int* __restrict__ r11, const int* __restrict__ c11, const float* __restrict__ v11,
                              const int* __restrict__ r22, const int* __restrict__ c22, const float* __restrict__ v22,
                              const int* __restrict__ r33, const int* __restrict__ c33, const float* __restrict__ v33,
                              const int* __restrict__ r01, const int* __restrict__ c01, const float* __restrict__ v01,
                              const int* __restrict__ r02, const int* __restrict__ c02, const float* __restrict__ v02,
                              const int* __restrict__ r03, const int* __restrict__ c03, const float* __restrict__ v03) {
    int b = blockIdx.x, t = threadIdx.x;
    const int* rows; const int* cols; const float* vals; int E, cuoff, eoff, b0;
    if (b < H11)      { rows = r11; cols = c11; vals = v11; E = E11; cuoff = CU11; eoff = EO11; b0 = 0; }
    else if (b < H22) { rows = r22; cols = c22; vals = v22; E = E22; cuoff = CU22; eoff = EO22; b0 = H11; }
    else if (b < H33) { rows = r33; cols = c33; vals = v33; E = E33; cuoff = CU33; eoff = EO33; b0 = H22; }
    else if (b < H01) { rows = r01; cols = c01; vals = v01; E = E01; cuoff = CU01; eoff = EO01; b0 = H33; }
    else if (b < H02) { rows = r02; cols = c02; vals = v02; E = E02; cuoff = CU02; eoff = EO02; b0 = H01; }
    else              { rows = r03; cols = c03; vals = v03; E = E03; cuoff = CU03; eoff = EO03; b0 = H02; }
    int e0 = (b - b0) * 1024 + t;
#pragma unroll
    for (int j = 0; j < 4; j++) {
        int e = e0 + j * 256;
        if (e < E) {
            int slot = atomicAdd(&g_cu[cuoff + rows[e]], 1);
            g_cols[eoff + slot] = cols[e];
            g_vals[eoff + slot] = vals[e];
        }
    }
}

// ---------------- spMM core: warp per row, lane holds 4 cols, edge-unrolled x4 ----------------
__device__ __forceinline__ float4 spmm_row_f4(const int* __restrict__ rp, const int* __restrict__ cs,
                                              const float* __restrict__ vs, const float4* __restrict__ x4,
                                              int row, int lane) {
    int s = rp[row], e = rp[row + 1];
    float4 acc = make_float4(0.f, 0.f, 0.f, 0.f);
    int i = s;
    for (; i + 3 < e; i += 4) {
        int c0 = cs[i], c1 = cs[i + 1], c2 = cs[i + 2], c3 = cs[i + 3];
        float v0 = vs[i], v1 = vs[i + 1], v2 = vs[i + 2], v3 = vs[i + 3];
        float4 a = x4[(size_t)c0 * 32 + lane];
        float4 b = x4[(size_t)c1 * 32 + lane];
        float4 c = x4[(size_t)c2 * 32 + lane];
        float4 d = x4[(size_t)c3 * 32 + lane];
        acc.x = fmaf(v0, a.x, fmaf(v1, b.x, fmaf(v2, c.x, fmaf(v3, d.x, acc.x))));
        acc.y = fmaf(v0, a.y, fmaf(v1, b.y, fmaf(v2, c.y, fmaf(v3, d.y, acc.y))));
        acc.z = fmaf(v0, a.z, fmaf(v1, b.z, fmaf(v2, c.z, fmaf(v3, d.z, acc.z))));
        acc.w = fmaf(v0, a.w, fmaf(v1, b.w, fmaf(v2, c.w, fmaf(v3, d.w, acc.w))));
    }
    for (; i < e; i++) {
        int c0 = cs[i]; float v0 = vs[i];
        float4 a = x4[(size_t)c0 * 32 + lane];
        acc.x = fmaf(v0, a.x, acc.x);
        acc.y = fmaf(v0, a.y, acc.y);
        acc.z = fmaf(v0, a.z, acc.z);
        acc.w = fmaf(v0, a.w, acc.w);
    }
    return acc;
}

__device__ __forceinline__ float4 relu4(float4 a) {
    return make_float4(fmaxf(a.x, 0.f), fmaxf(a.y, 0.f), fmaxf(a.z, 0.f), fmaxf(a.w, 0.f));
}

__device__ __forceinline__ void store_relu_f4(float4 acc, float* __restrict__ y, int row, int lane) {
    ((float4*)y)[(size_t)row * 32 + lane] = relu4(acc);
}

__device__ __forceinline__ void store_norm_f4(float4 acc, float* __restrict__ y, int row, int lane) {
    float sq = acc.x * acc.x + acc.y * acc.y + acc.z * acc.z + acc.w * acc.w;
#pragma unroll
    for (int o = 16; o > 0; o >>= 1) sq += __shfl_xor_sync(~0u, sq, o);
    float s = 1.f / (sqrtf(sq) + 1e-9f);
    ((float4*)y)[(size_t)row * 32 + lane] = make_float4(acc.x * s, acc.y * s, acc.z * s, acc.w * s);
}

// ---------------- FFMA2 GEMM from smem tile: y[r0..r0+64,128] = xs @ W + b ----------------
__device__ __forceinline__ void gemm64_smem(const float* __restrict__ W, const float* __restrict__ bias,
                                            float* __restrict__ y, int nrows, int r0, const float* xs) {
    int t = threadIdx.x;
    const float4* xs4 = (const float4*)xs;
    int cg = t & 31;   // cols 4cg .. 4cg+3
    int rg = t >> 5;   // rows rg*8 .. +8
    const float4* Wc = (const float4*)W;
    float4 b4 = ((const float4*)bias)[cg];
    ull acc[8][2];
#pragma unroll
    for (int r = 0; r < 8; r++) { acc[r][0] = pack2(b4.x, b4.y); acc[r][1] = pack2(b4.z, b4.w); }
    const float4* xr = xs4 + rg * 8 * 32;
    for (int k4 = 0; k4 < 32; k4++) {
        float4 xv[8];
#pragma unroll
        for (int r = 0; r < 8; r++) xv[r] = xr[r * 32 + k4];
#pragma unroll
        for (int kk = 0; kk < 4; kk++) {
            float4 wv = Wc[(k4 * 4 + kk) * 32 + cg];
            ull wp0 = pack2(wv.x, wv.y);
            ull wp1 = pack2(wv.z, wv.w);
#pragma unroll
            for (int r = 0; r < 8; r++) {
                float xsv = (kk == 0) ? xv[r].x : (kk == 1) ? xv[r].y : (kk == 2) ? xv[r].z : xv[r].w;
                ull xp = pack2(xsv, xsv);
                acc[r][0] = fma2(xp, wp0, acc[r][0]);
                acc[r][1] = fma2(xp, wp1, acc[r][1]);
            }
        }
    }
#pragma unroll
    for (int r = 0; r < 8; r++) {
        int gr = r0 + rg * 8 + r;
        if (gr < nrows) {
            float2 lo = unpack2(acc[r][0]);
            float2 hi = unpack2(acc[r][1]);
            ((float4*)y)[(size_t)gr * 32 + cg] = make_float4(lo.x, lo.y, hi.x, hi.y);
        }
    }
}

// ---------------- Stage AB: fused spmm1+gemm (t1, t2) + full t3 chain ----------------
__global__ void k_stageAB(const float* __restrict__ f1, const float* __restrict__ f2,
                          const float* __restrict__ f3, const float* __restrict__ W3,
                          const float* __restrict__ b3, const float* __restrict__ W1_2,
                          const float* __restrict__ b1_2, const float* __restrict__ W2_2,
                          const float* __restrict__ b2_2, const float* __restrict__ W3_2,
                          const float* __restrict__ b3_2) {
    __shared__ float xs[64 * 128];
    float4* xs4 = (float4*)xs;
    int b = blockIdx.x, t = threadIdx.x, lane = t & 31, w = t >> 5;

    if (b < 470) {
        const float4* src; const int* rp; const int* cs; const float* vs;
        const float* W; const float* bias; float* y; int nrows, r0;
        if (b < 313) {
            src = (const float4*)f1; rp = g_rp + RP11; cs = g_cols + EO11; vs = g_vals + EO11;
            W = W1_2; bias = b1_2; y = g_t1; nrows = N_WORD; r0 = b * 64;
        } else {
            src = (const float4*)f2; rp = g_rp + RP22; cs = g_cols + EO22; vs = g_vals + EO22;
            W = W2_2; bias = b2_2; y = g_t2; nrows = N_ENT; r0 = (b - 313) * 64;
        }
        // spmm phase: warp w produces rows w*8 .. w*8+7 of the tile into smem
#pragma unroll 1
        for (int i = 0; i < 8; i++) {
            int rl = w * 8 + i;
            int row = r0 + rl;
            float4 acc = make_float4(0.f, 0.f, 0.f, 0.f);
            if (row < nrows) acc = spmm_row_f4(rp, cs, vs, src, row, lane);
            xs4[rl * 32 + lane] = relu4(acc);
        }
        __syncthreads();
        // gemm phase straight from smem
        gemm64_smem(W, bias, y, nrows, r0, xs);
    } else {
        // ---- entire type-3 chain in one block ----
        // gemm1: xs[r,:] = f3[r,:] @ W3 + b3  (60 rows; rows 60..63 zeroed)
        for (int i = t; i < 64 * DIM; i += 256) {
            int r = i >> 7, c = i & 127;
            float a = 0.f;
            if (r < N_POS) {
                a = b3[c];
#pragma unroll 4
                for (int k = 0; k < D_POS_IN; k++)
                    a = fmaf(f3[r * D_POS_IN + k], W3[k * DIM + c], a);
            }
            xs[i] = a;
        }
        __syncthreads();
        // spmm1 from smem into registers
        float4 res[8];
#pragma unroll 1
        for (int i = 0; i < 8; i++) {
            int rl = w * 8 + i;
            res[i] = make_float4(0.f, 0.f, 0.f, 0.f);
            if (rl < N_POS)
                res[i] = spmm_row_f4(g_rp + RP33, g_cols + EO33, g_vals + EO33,
                                     (const float4*)xs, rl, lane);
        }
        __syncthreads();
#pragma unroll
        for (int i = 0; i < 8; i++) {
            int rl = w * 8 + i;
            xs4[rl * 32 + lane] = relu4(res[i]);
        }
        __syncthreads();
        // gemm2 from smem -> g_t3a
        gemm64_smem(W3_2, b3_2, g_t3a, N_POS, 0, xs);
    }
}

// ---------------- Stage C: spmm2(t1) + spmm2(t2) + t3 spmm2 ----------------
__global__ void k_stageC() {
    int b = blockIdx.x, t = threadIdx.x, lane = t & 31, w = t >> 5;
    if (b < 2500) {
        int row = b * 8 + w;
        float4 acc = spmm_row_f4(g_rp + RP11, g_cols + EO11, g_vals + EO11, (const float4*)g_t1, row, lane);
        store_relu_f4(acc, g_h1, row, lane);
    } else if (b < 3750) {
        int row = (b - 2500) * 8 + w;
        float4 acc = spmm_row_f4(g_rp + RP22, g_cols + EO22, g_vals + EO22, (const float4*)g_t2, row, lane);
        store_relu_f4(acc, g_h2, row, lane);
    } else {
        int row = (b - 3750) * 8 + w;
        if (row < N_POS) {
            float4 acc = spmm_row_f4(g_rp + RP33, g_cols + EO33, g_vals + EO33, (const float4*)g_t3a, row, lane);
            store_relu_f4(acc, g_h3, row, lane);
        }
    }
}

// ---------------- Stage D (512 thr): out1 + out2 + out3 ----------------
__global__ void k_stageD(const float* __restrict__ wemb, float* __restrict__ out) {
    int b = blockIdx.x, t = threadIdx.x, lane = t & 31, w = t >> 5;
    if (b < 625) {
        int row = b * 16 + w;
        float4 acc = spmm_row_f4(g_rp + RP01, g_cols + EO01, g_vals + EO01, (const float4*)g_h1, row, lane);
        store_norm_f4(acc, out, row, lane);
    } else if (b < 10625) {
        __shared__ float red[16];
        int row = b - 625;
        const int* rp = g_rp + RP02;
        const int* cs = g_cols + EO02;
        const float* vs = g_vals + EO02;
        int s = rp[row], e = rp[row + 1];
        float acc0 = 0.f, acc1 = 0.f;
        if (t < DIM) {
            int i = s;
            for (; i + 1 < e; i += 2) {
                int c0 = cs[i], c1 = cs[i + 1];
                acc0 = fmaf(vs[i], g_h2[(size_t)c0 * DIM + t], acc0);
                acc1 = fmaf(vs[i + 1], g_h2[(size_t)c1 * DIM + t], acc1);
            }
            if (i < e) acc0 = fmaf(vs[i], g_h2[(size_t)cs[i] * DIM + t], acc0);
        } else if (t < DIM + D_WEMB) {
            int tc = t - DIM;
            int i = s;
            for (; i + 1 < e; i += 2) {
                int c0 = cs[i], c1 = cs[i + 1];
                acc0 = fmaf(vs[i], wemb[(size_t)c0 * D_WEMB + tc], acc0);
                acc1 = fmaf(vs[i + 1], wemb[(size_t)c1 * D_WEMB + tc], acc1);
            }
            if (i < e) acc0 = fmaf(vs[i], wemb[(size_t)cs[i] * D_WEMB + tc], acc0);
        }
        float acc = acc0 + acc1;
        float sq = acc * acc;
#pragma unroll
        for (int o = 16; o > 0; o >>= 1) sq += __shfl_xor_sync(~0u, sq, o);
        if (lane == 0) red[w] = sq;
        __syncthreads();
        if (t == 0) {
            float sum = 0.f;
#pragma unroll
            for (int i = 0; i < 16; i++) sum += red[i];
            red[0] = 1.f / (sqrtf(sum) + 1e-9f);
        }
        __syncthreads();
        float scale = red[0];
        if (t < DIM + D_WEMB)
            out[(size_t)N_DOC * DIM + (size_t)row * (DIM + D_WEMB) + t] = acc * scale;
    } else {
        int row = (b - 10625) * 16 + w;
        float4 acc = spmm_row_f4(g_rp + RP03, g_cols + EO03, g_vals + EO03, (const float4*)g_h3, row, lane);
        float* out3 = out + (size_t)N_DOC * (DIM + DIM + D_WEMB);
        store_norm_f4(acc, out3, row, lane);
    }
}

// ---------------- host ----------------
extern "C" void kernel_launch(void* const* d_in, const int* in_sizes, int n_in,
                              void* d_out, int out_size) {
    const float* f1 = (const float*)d_in[0];
    const float* f2 = (const float*)d_in[1];
    const float* f3 = (const float*)d_in[2];
    const float* wemb = (const float*)d_in[3];
    const int* a11_r = (const int*)d_in[4];  const int* a11_c = (const int*)d_in[5];  const float* a11_v = (const float*)d_in[6];
    const int* a22_r = (const int*)d_in[7];  const int* a22_c = (const int*)d_in[8];  const float* a22_v = (const float*)d_in[9];
    const int* a33_r = (const int*)d_in[10]; const int* a33_c = (const int*)d_in[11]; const float* a33_v = (const float*)d_in[12];
    const int* a01_r = (const int*)d_in[13]; const int* a01_c = (const int*)d_in[14]; const float* a01_v = (const float*)d_in[15];
    const int* a02_r = (const int*)d_in[16]; const int* a02_c = (const int*)d_in[17]; const float* a02_v = (const float*)d_in[18];
    const int* a03_r = (const int*)d_in[19]; const int* a03_c = (const int*)d_in[20]; const float* a03_v = (const float*)d_in[21];
    const float* W3 = (const float*)d_in[22];   const float* b3 = (const float*)d_in[23];
    const float* W1_2 = (const float*)d_in[24]; const float* b1_2 = (const float*)d_in[25];
    const float* W2_2 = (const float*)d_in[26]; const float* b2_2 = (const float*)d_in[27];
    const float* W3_2 = (const float*)d_in[28]; const float* b3_2 = (const float*)d_in[29];

    float* out = (float*)d_out;

    // CSR build
    k_zero<<<(CU_TOT + 255) / 256, 256>>>();
    k_hist_all<<<H03, 256>>>(a11_r, a22_r, a33_r, a01_r, a02_r, a03_r);
    k_scan_all<<<6, 1024>>>();
    k_scatter_all<<<H03, 256>>>(a11_r, a11_c, a11_v, a22_r, a22_c, a22_v,
                                a33_r, a33_c, a33_v, a01_r, a01_c, a01_v,
                                a02_r, a02_c, a02_v, a03_r, a03_c, a03_v);

    // compute: 3 launches
    k_stageAB<<<471, 256>>>(f1, f2, f3, W3, b3, W1_2, b1_2, W2_2, b2_2, W3_2, b3_2);
    k_stageC<<<3758, 256>>>();
    k_stageD<<<11250, 512>>>(wemb, out);
}

// round 6
// speedup vs baseline: 1.2232x; 1.2232x over previous
#include <cuda_runtime.h>
#include <math.h>

#define N_DOC 10000
#define N_WORD 20000
#define N_ENT 10000
#define N_POS 60
#define DIM 128
#define D_POS_IN 60
#define D_WEMB 300
#define E11 320000
#define E22 160000
#define E33 3600
#define E01 300000
#define E02 100000
#define E03 150000

typedef unsigned long long ull;

// merged offsets (compile time)
enum { CU11 = 0, CU22 = 20000, CU33 = 30000, CU01 = 30060, CU02 = 40060, CU03 = 50060, CU_TOT = 60060 };
enum { RP11 = 0, RP22 = 20001, RP33 = 30002, RP01 = 30063, RP02 = 40064, RP03 = 50065, RP_TOT = 60066 };
enum { EO11 = 0, EO22 = 320000, EO33 = 480000, EO01 = 483600, EO02 = 783600, EO03 = 883600, E_TOT = 1033600 };

// hist & scatter: 4 edges/thread (1024 edges/block)
enum { H11 = 313, H22 = 470, H33 = 474, H01 = 767, H02 = 865, H03 = 1012 };

// ---------------- scratch ----------------
__device__ int   g_cu[CU_TOT];
__device__ int   g_rp[RP_TOT];
__device__ int   g_cols[E_TOT];
__device__ float g_vals[E_TOT];

__device__ float g_h1a[N_WORD * DIM];
__device__ float g_t1[N_WORD * DIM];
__device__ float g_h1[N_WORD * DIM];
__device__ float g_h2a[N_ENT * DIM];
__device__ float g_t2[N_ENT * DIM];
__device__ float g_h2[N_ENT * DIM];
__device__ float g_t3a[N_POS * DIM];
__device__ float g_t3b[N_POS * DIM];
__device__ float g_h3[N_POS * DIM];

// ---------------- packed fp32 helpers ----------------
__device__ __forceinline__ ull fma2(ull a, ull b, ull c) {
    ull d;
    asm("fma.rn.f32x2 %0, %1, %2, %3;" : "=l"(d) : "l"(a), "l"(b), "l"(c));
    return d;
}
__device__ __forceinline__ ull pack2(float lo, float hi) {
    ull d;
    asm("mov.b64 %0, {%1, %2};" : "=l"(d) : "f"(lo), "f"(hi));
    return d;
}
__device__ __forceinline__ float2 unpack2(ull v) {
    float2 r;
    asm("mov.b64 {%0, %1}, %2;" : "=f"(r.x), "=f"(r.y) : "l"(v));
    return r;
}

// ---------------- CSR build ----------------
__global__ void k_zero() {
    int i = blockIdx.x * blockDim.x + threadIdx.x;
    if (i < CU_TOT) g_cu[i] = 0;
}

// hist + (piggybacked, dependency-free) t3 gemm1: g_t3a = f3 @ W3 + b3
__global__ void k_hist_all(const int* __restrict__ r11, const int* __restrict__ r22,
                           const int* __restrict__ r33, const int* __restrict__ r01,
                           const int* __restrict__ r02, const int* __restrict__ r03,
                           const float* __restrict__ f3, const float* __restrict__ W3,
                           const float* __restrict__ b3) {
    int b = blockIdx.x, t = threadIdx.x;
    if (b >= H03) {
        // 15 blocks x 4 rows: t3 gemm1 (60x60 @ 60x128), inputs only -> no dependency
        int r0 = (b - H03) * 4;
#pragma unroll
        for (int i = t; i < 4 * DIM; i += 256) {
            int r = r0 + (i >> 7), c = i & 127;
            float a = b3[c];
#pragma unroll 4
            for (int k = 0; k < D_POS_IN; k++)
                a = fmaf(f3[r * D_POS_IN + k], W3[k * DIM + c], a);
            g_t3a[r * DIM + c] = a;
        }
        return;
    }
    const int* rows; int E, off, b0;
    if (b < H11)      { rows = r11; E = E11; off = CU11; b0 = 0; }
    else if (b < H22) { rows = r22; E = E22; off = CU22; b0 = H11; }
    else if (b < H33) { rows = r33; E = E33; off = CU33; b0 = H22; }
    else if (b < H01) { rows = r01; E = E01; off = CU01; b0 = H33; }
    else if (b < H02) { rows = r02; E = E02; off = CU02; b0 = H01; }
    else              { rows = r03; E = E03; off = CU03; b0 = H02; }
    int e0 = (b - b0) * 1024 + t;
#pragma unroll
    for (int j = 0; j < 4; j++) {
        int e = e0 + j * 256;
        if (e < E) atomicAdd(&g_cu[off + rows[e]], 1);
    }
}

__global__ void k_scan_all() {
    __shared__ int wsum[32];
    const int ns[6]  = {N_WORD, N_ENT, N_POS, N_DOC, N_DOC, N_DOC};
    const int cuo[6] = {CU11, CU22, CU33, CU01, CU02, CU03};
    const int rpo[6] = {RP11, RP22, RP33, RP01, RP02, RP03};
    int g = blockIdx.x;
    int n = ns[g];
    int* cnt = g_cu + cuo[g];
    int* rp  = g_rp + rpo[g];
    int tid = threadIdx.x;  // 1024
    int chunk = (n + 1023) >> 10;
    int base = tid * chunk;
    int end = base + chunk; if (end > n) end = n;
    int s = 0;
    for (int i = base; i < end && i >= base; i++) s += cnt[i];
    int lane = tid & 31, w = tid >> 5;
    int v = s;
#pragma unroll
    for (int o = 1; o < 32; o <<= 1) { int u = __shfl_up_sync(~0u, v, o); if (lane >= o) v += u; }
    if (lane == 31) wsum[w] = v;
    __syncthreads();
    if (w == 0) {
        int x = wsum[lane];
#pragma unroll
        for (int o = 1; o < 32; o <<= 1) { int u = __shfl_up_sync(~0u, x, o); if (lane >= o) x += u; }
        wsum[lane] = x;
    }
    __syncthreads();
    int excl = v - s + (w > 0 ? wsum[w - 1] : 0);
    int run = excl;
    for (int i = base; i < end && i >= base; i++) {
        int c = cnt[i];
        cnt[i] = run;
        rp[i] = run;
        run += c;
    }
    if (end == n || base >= n) rp[n] = run;
}

__global__ void k_scatter_all(const int* __restrict__ r11, const int* __restrict__ c11, const float* __restrict__ v11,
                              const int* __restrict__ r22, const int* __restrict__ c22, const float* __restrict__ v22,
                              const int* __restrict__ r33, const int* __restrict__ c33, const float* __restrict__ v33,
                              const int* __restrict__ r01, const int* __restrict__ c01, const float* __restrict__ v01,
                              const int* __restrict__ r02, const int* __restrict__ c02, const float* __restrict__ v02,
                              const int* __restrict__ r03, const int* __restrict__ c03, const float* __restrict__ v03) {
    int b = blockIdx.x, t = threadIdx.x;
    const int* rows; const int* cols; const float* vals; int E, cuoff, eoff, b0;
    if (b < H11)      { rows = r11; cols = c11; vals = v11; E = E11; cuoff = CU11; eoff = EO11; b0 = 0; }
    else if (b < H22) { rows = r22; cols = c22; vals = v22; E = E22; cuoff = CU22; eoff = EO22; b0 = H11; }
    else if (b < H33) { rows = r33; cols = c33; vals = v33; E = E33; cuoff = CU33; eoff = EO33; b0 = H22; }
    else if (b < H01) { rows = r01; cols = c01; vals = v01; E = E01; cuoff = CU01; eoff = EO01; b0 = H33; }
    else if (b < H02) { rows = r02; cols = c02; vals = v02; E = E02; cuoff = CU02; eoff = EO02; b0 = H01; }
    else              { rows = r03; cols = c03; vals = v03; E = E03; cuoff = CU03; eoff = EO03; b0 = H02; }
    int e0 = (b - b0) * 1024 + t;
#pragma unroll
    for (int j = 0; j < 4; j++) {
        int e = e0 + j * 256;
        if (e < E) {
            int slot = atomicAdd(&g_cu[cuoff + rows[e]], 1);
            g_cols[eoff + slot] = cols[e];
            g_vals[eoff + slot] = vals[e];
        }
    }
}

// ---------------- spMM core: warp per row, lane holds 4 cols, edge-unrolled x4 ----------------
__device__ __forceinline__ float4 spmm_row_f4(const int* __restrict__ rp, const int* __restrict__ cs,
                                              const float* __restrict__ vs, const float4* __restrict__ x4,
                                              int row, int lane) {
    int s = rp[row], e = rp[row + 1];
    float4 acc = make_float4(0.f, 0.f, 0.f, 0.f);
    int i = s;
    for (; i + 3 < e; i += 4) {
        int c0 = cs[i], c1 = cs[i + 1], c2 = cs[i + 2], c3 = cs[i + 3];
        float v0 = vs[i], v1 = vs[i + 1], v2 = vs[i + 2], v3 = vs[i + 3];
        float4 a = x4[(size_t)c0 * 32 + lane];
        float4 b = x4[(size_t)c1 * 32 + lane];
        float4 c = x4[(size_t)c2 * 32 + lane];
        float4 d = x4[(size_t)c3 * 32 + lane];
        acc.x = fmaf(v0, a.x, fmaf(v1, b.x, fmaf(v2, c.x, fmaf(v3, d.x, acc.x))));
        acc.y = fmaf(v0, a.y, fmaf(v1, b.y, fmaf(v2, c.y, fmaf(v3, d.y, acc.y))));
        acc.z = fmaf(v0, a.z, fmaf(v1, b.z, fmaf(v2, c.z, fmaf(v3, d.z, acc.z))));
        acc.w = fmaf(v0, a.w, fmaf(v1, b.w, fmaf(v2, c.w, fmaf(v3, d.w, acc.w))));
    }
    for (; i < e; i++) {
        int c0 = cs[i]; float v0 = vs[i];
        float4 a = x4[(size_t)c0 * 32 + lane];
        acc.x = fmaf(v0, a.x, acc.x);
        acc.y = fmaf(v0, a.y, acc.y);
        acc.z = fmaf(v0, a.z, acc.z);
        acc.w = fmaf(v0, a.w, acc.w);
    }
    return acc;
}

__device__ __forceinline__ void store_relu_f4(float4 acc, float* __restrict__ y, int row, int lane) {
    ((float4*)y)[(size_t)row * 32 + lane] =
        make_float4(fmaxf(acc.x, 0.f), fmaxf(acc.y, 0.f), fmaxf(acc.z, 0.f), fmaxf(acc.w, 0.f));
}

__device__ __forceinline__ void store_norm_f4(float4 acc, float* __restrict__ y, int row, int lane) {
    float sq = acc.x * acc.x + acc.y * acc.y + acc.z * acc.z + acc.w * acc.w;
#pragma unroll
    for (int o = 16; o > 0; o >>= 1) sq += __shfl_xor_sync(~0u, sq, o);
    float s = 1.f / (sqrtf(sq) + 1e-9f);
    ((float4*)y)[(size_t)row * 32 + lane] = make_float4(acc.x * s, acc.y * s, acc.z * s, acc.w * s);
}

// ---------------- Stage A: spmm1(t1) + spmm1(t2) + t3 spmm1 ----------------
__global__ void k_stageA(const float* __restrict__ f1, const float* __restrict__ f2) {
    int b = blockIdx.x, t = threadIdx.x, lane = t & 31, w = t >> 5;
    if (b < 2500) {
        int row = b * 8 + w;
        float4 acc = spmm_row_f4(g_rp + RP11, g_cols + EO11, g_vals + EO11, (const float4*)f1, row, lane);
        store_relu_f4(acc, g_h1a, row, lane);
    } else if (b < 3750) {
        int row = (b - 2500) * 8 + w;
        float4 acc = spmm_row_f4(g_rp + RP22, g_cols + EO22, g_vals + EO22, (const float4*)f2, row, lane);
        store_relu_f4(acc, g_h2a, row, lane);
    } else {
        int row = (b - 3750) * 8 + w;
        if (row < N_POS) {
            float4 acc = spmm_row_f4(g_rp + RP33, g_cols + EO33, g_vals + EO33, (const float4*)g_t3a, row, lane);
            store_relu_f4(acc, g_t3b, row, lane);
        }
    }
}

// ---------------- FFMA2 GEMM, 64-row tiles: y = x @ W + b ----------------
__device__ __forceinline__ void gemm64_f2(const float* __restrict__ x, const float* __restrict__ W,
                                          const float* __restrict__ bias, float* __restrict__ y,
                                          int nrows, int r0, float* xs) {
    int t = threadIdx.x;
    const float4* x4 = (const float4*)x;
    float4* xs4 = (float4*)xs;
    for (int i = t; i < 64 * 32; i += 256) {
        int gr = r0 + (i >> 5);
        xs4[i] = (gr < nrows) ? x4[(size_t)gr * 32 + (i & 31)] : make_float4(0.f, 0.f, 0.f, 0.f);
    }
    __syncthreads();
    int cg = t & 31;   // cols 4cg .. 4cg+3
    int rg = t >> 5;   // rows rg*8 .. +8
    const float4* Wc = (const float4*)W;
    float4 b4 = ((const float4*)bias)[cg];
    ull acc[8][2];
#pragma unroll
    for (int r = 0; r < 8; r++) { acc[r][0] = pack2(b4.x, b4.y); acc[r][1] = pack2(b4.z, b4.w); }
    const float4* xr = xs4 + rg * 8 * 32;
    for (int k4 = 0; k4 < 32; k4++) {
        float4 xv[8];
#pragma unroll
        for (int r = 0; r < 8; r++) xv[r] = xr[r * 32 + k4];
#pragma unroll
        for (int kk = 0; kk < 4; kk++) {
            float4 wv = Wc[(k4 * 4 + kk) * 32 + cg];
            ull wp0 = pack2(wv.x, wv.y);
            ull wp1 = pack2(wv.z, wv.w);
#pragma unroll
            for (int r = 0; r < 8; r++) {
                float xsv = (kk == 0) ? xv[r].x : (kk == 1) ? xv[r].y : (kk == 2) ? xv[r].z : xv[r].w;
                ull xp = pack2(xsv, xsv);
                acc[r][0] = fma2(xp, wp0, acc[r][0]);
                acc[r][1] = fma2(xp, wp1, acc[r][1]);
            }
        }
    }
#pragma unroll
    for (int r = 0; r < 8; r++) {
        int gr = r0 + rg * 8 + r;
        if (gr < nrows) {
            float2 lo = unpack2(acc[r][0]);
            float2 hi = unpack2(acc[r][1]);
            ((float4*)y)[(size_t)gr * 32 + cg] = make_float4(lo.x, lo.y, hi.x, hi.y);
        }
    }
}

// ---------------- Stage B: gemm(t1) + gemm(t2) + t3 gemm2 ----------------
__global__ void k_stageB(const float* __restrict__ W1_2, const float* __restrict__ b1_2,
                         const float* __restrict__ W2_2, const float* __restrict__ b2_2,
                         const float* __restrict__ W3_2, const float* __restrict__ b3_2) {
    __shared__ float xs[64 * 128];
    int b = blockIdx.x;
    if (b < 313)      gemm64_f2(g_h1a, W1_2, b1_2, g_t1, N_WORD, b * 64, xs);
    else if (b < 470) gemm64_f2(g_h2a, W2_2, b2_2, g_t2, N_ENT, (b - 313) * 64, xs);
    else              gemm64_f2(g_t3b, W3_2, b3_2, g_t3a, N_POS, 0, xs);
}

// ---------------- Stage C: spmm2(t1) + spmm2(t2) + t3 spmm2 ----------------
__global__ void k_stageC() {
    int b = blockIdx.x, t = threadIdx.x, lane = t & 31, w = t >> 5;
    if (b < 2500) {
        int row = b * 8 + w;
        float4 acc = spmm_row_f4(g_rp + RP11, g_cols + EO11, g_vals + EO11, (const float4*)g_t1, row, lane);
        store_relu_f4(acc, g_h1, row, lane);
    } else if (b < 3750) {
        int row = (b - 2500) * 8 + w;
        float4 acc = spmm_row_f4(g_rp + RP22, g_cols + EO22, g_vals + EO22, (const float4*)g_t2, row, lane);
        store_relu_f4(acc, g_h2, row, lane);
    } else {
        int row = (b - 3750) * 8 + w;
        if (row < N_POS) {
            float4 acc = spmm_row_f4(g_rp + RP33, g_cols + EO33, g_vals + EO33, (const float4*)g_t3a, row, lane);
            store_relu_f4(acc, g_h3, row, lane);
        }
    }
}

// ---------------- Stage D (512 thr): out1 + out2 + out3 ----------------
__global__ void k_stageD(const float* __restrict__ wemb, float* __restrict__ out) {
    int b = blockIdx.x, t = threadIdx.x, lane = t & 31, w = t >> 5;
    if (b < 625) {
        int row = b * 16 + w;
        float4 acc = spmm_row_f4(g_rp + RP01, g_cols + EO01, g_vals + EO01, (const float4*)g_h1, row, lane);
        store_norm_f4(acc, out, row, lane);
    } else if (b < 10625) {
        __shared__ float red[16];
        int row = b - 625;
        const int* rp = g_rp + RP02;
        const int* cs = g_cols + EO02;
        const float* vs = g_vals + EO02;
        int s = rp[row], e = rp[row + 1];
        float acc0 = 0.f, acc1 = 0.f, acc2 = 0.f, acc3 = 0.f;
        if (t < DIM) {
            int i = s;
            for (; i + 3 < e; i += 4) {
                acc0 = fmaf(vs[i],     g_h2[(size_t)cs[i] * DIM + t],     acc0);
                acc1 = fmaf(vs[i + 1], g_h2[(size_t)cs[i + 1] * DIM + t], acc1);
                acc2 = fmaf(vs[i + 2], g_h2[(size_t)cs[i + 2] * DIM + t], acc2);
                acc3 = fmaf(vs[i + 3], g_h2[(size_t)cs[i + 3] * DIM + t], acc3);
            }
            for (; i < e; i++) acc0 = fmaf(vs[i], g_h2[(size_t)cs[i] * DIM + t], acc0);
        } else if (t < DIM + D_WEMB) {
            int tc = t - DIM;
            int i = s;
            for (; i + 3 < e; i += 4) {
                acc0 = fmaf(vs[i],     wemb[(size_t)cs[i] * D_WEMB + tc],     acc0);
                acc1 = fmaf(vs[i + 1], wemb[(size_t)cs[i + 1] * D_WEMB + tc], acc1);
                acc2 = fmaf(vs[i + 2], wemb[(size_t)cs[i + 2] * D_WEMB + tc], acc2);
                acc3 = fmaf(vs[i + 3], wemb[(size_t)cs[i + 3] * D_WEMB + tc], acc3);
            }
            for (; i < e; i++) acc0 = fmaf(vs[i], wemb[(size_t)cs[i] * D_WEMB + tc], acc0);
        }
        float acc = (acc0 + acc1) + (acc2 + acc3);
        float sq = acc * acc;
#pragma unroll
        for (int o = 16; o > 0; o >>= 1) sq += __shfl_xor_sync(~0u, sq, o);
        if (lane == 0) red[w] = sq;
        __syncthreads();
        if (t == 0) {
            float sum = 0.f;
#pragma unroll
            for (int i = 0; i < 16; i++) sum += red[i];
            red[0] = 1.f / (sqrtf(sum) + 1e-9f);
        }
        __syncthreads();
        float scale = red[0];
        if (t < DIM + D_WEMB)
            out[(size_t)N_DOC * DIM + (size_t)row * (DIM + D_WEMB) + t] = acc * scale;
    } else {
        int row = (b - 10625) * 16 + w;
        float4 acc = spmm_row_f4(g_rp + RP03, g_cols + EO03, g_vals + EO03, (const float4*)g_h3, row, lane);
        float* out3 = out + (size_t)N_DOC * (DIM + DIM + D_WEMB);
        store_norm_f4(acc, out3, row, lane);
    }
}

// ---------------- host ----------------
extern "C" void kernel_launch(void* const* d_in, const int* in_sizes, int n_in,
                              void* d_out, int out_size) {
    const float* f1 = (const float*)d_in[0];
    const float* f2 = (const float*)d_in[1];
    const float* f3 = (const float*)d_in[2];
    const float* wemb = (const float*)d_in[3];
    const int* a11_r = (const int*)d_in[4];  const int* a11_c = (const int*)d_in[5];  const float* a11_v = (const float*)d_in[6];
    const int* a22_r = (const int*)d_in[7];  const int* a22_c = (const int*)d_in[8];  const float* a22_v = (const float*)d_in[9];
    const int* a33_r = (const int*)d_in[10]; const int* a33_c = (const int*)d_in[11]; const float* a33_v = (const float*)d_in[12];
    const int* a01_r = (const int*)d_in[13]; const int* a01_c = (const int*)d_in[14]; const float* a01_v = (const float*)d_in[15];
    const int* a02_r = (const int*)d_in[16]; const int* a02_c = (const int*)d_in[17]; const float* a02_v = (const float*)d_in[18];
    const int* a03_r = (const int*)d_in[19]; const int* a03_c = (const int*)d_in[20]; const float* a03_v = (const float*)d_in[21];
    const float* W3 = (const float*)d_in[22];   const float* b3 = (const float*)d_in[23];
    const float* W1_2 = (const float*)d_in[24]; const float* b1_2 = (const float*)d_in[25];
    const float* W2_2 = (const float*)d_in[26]; const float* b2_2 = (const float*)d_in[27];
    const float* W3_2 = (const float*)d_in[28]; const float* b3_2 = (const float*)d_in[29];

    float* out = (float*)d_out;

    // CSR build (t3 gemm1 piggybacked on hist — dependency-free)
    k_zero<<<(CU_TOT + 255) / 256, 256>>>();
    k_hist_all<<<H03 + 15, 256>>>(a11_r, a22_r, a33_r, a01_r, a02_r, a03_r, f3, W3, b3);
    k_scan_all<<<6, 1024>>>();
    k_scatter_all<<<H03, 256>>>(a11_r, a11_c, a11_v, a22_r, a22_c, a22_v,
                                a33_r, a33_c, a33_v, a01_r, a01_c, a01_v,
                                a02_r, a02_c, a02_v, a03_r, a03_c, a03_v);

    // compute: 4 launches
    k_stageA<<<3758, 256>>>(f1, f2);
    k_stageB<<<471, 256>>>(W1_2, b1_2, W2_2, b2_2, W3_2, b3_2);
    k_stageC<<<3758, 256>>>();
    k_stageD<<<11250, 512>>>(wemb, out);
}

// round 7
// speedup vs baseline: 1.2443x; 1.0173x over previous
#include <cuda_runtime.h>
#include <math.h>

#define N_DOC 10000
#define N_WORD 20000
#define N_ENT 10000
#define N_POS 60
#define DIM 128
#define D_POS_IN 60
#define D_WEMB 300
#define E11 320000
#define E22 160000
#define E33 3600
#define E01 300000
#define E02 100000
#define E03 150000

typedef unsigned long long ull;

// merged offsets (compile time)
enum { CU11 = 0, CU22 = 20000, CU33 = 30000, CU01 = 30060, CU02 = 40060, CU03 = 50060, CU_TOT = 60060 };
enum { RP11 = 0, RP22 = 20001, RP33 = 30002, RP01 = 30063, RP02 = 40064, RP03 = 50065, RP_TOT = 60066 };
enum { EO11 = 0, EO22 = 320000, EO33 = 480000, EO01 = 483600, EO02 = 783600, EO03 = 883600, E_TOT = 1033600 };

// hist & scatter: 4 edges/thread (1024 edges/block)
enum { H11 = 313, H22 = 470, H33 = 474, H01 = 767, H02 = 865, H03 = 1012 };

// stageD layout: 448 threads (14 warps)
enum { D_OUT1 = 715, D_OUT2 = D_OUT1 + 10000, D_OUT3 = D_OUT2 + 715, D_ZERO = D_OUT3 + 59 };

// ---------------- scratch ----------------
__device__ int   g_cu[CU_TOT];
__device__ int   g_rp[RP_TOT];
__device__ int2  g_ecv[E_TOT];   // interleaved (col, val_bits)

__device__ float g_h1a[N_WORD * DIM];
__device__ float g_t1[N_WORD * DIM];
__device__ float g_h1[N_WORD * DIM];
__device__ float g_h2a[N_ENT * DIM];
__device__ float g_t2[N_ENT * DIM];
__device__ float g_h2[N_ENT * DIM];
__device__ float g_t3a[N_POS * DIM];
__device__ float g_t3b[N_POS * DIM];
__device__ float g_h3[N_POS * DIM];

// ---------------- packed fp32 helpers ----------------
__device__ __forceinline__ ull fma2(ull a, ull b, ull c) {
    ull d;
    asm("fma.rn.f32x2 %0, %1, %2, %3;" : "=l"(d) : "l"(a), "l"(b), "l"(c));
    return d;
}
__device__ __forceinline__ ull pack2(float lo, float hi) {
    ull d;
    asm("mov.b64 %0, {%1, %2};" : "=l"(d) : "f"(lo), "f"(hi));
    return d;
}
__device__ __forceinline__ float2 unpack2(ull v) {
    float2 r;
    asm("mov.b64 {%0, %1}, %2;" : "=f"(r.x), "=f"(r.y) : "l"(v));
    return r;
}

// ---------------- CSR build ----------------
// hist + (piggybacked, dependency-free) t3 gemm1: g_t3a = f3 @ W3 + b3
__global__ void k_hist_all(const int* __restrict__ r11, const int* __restrict__ r22,
                           const int* __restrict__ r33, const int* __restrict__ r01,
                           const int* __restrict__ r02, const int* __restrict__ r03,
                           const float* __restrict__ f3, const float* __restrict__ W3,
                           const float* __restrict__ b3) {
    int b = blockIdx.x, t = threadIdx.x;
    if (b >= H03) {
        int r0 = (b - H03) * 4;
#pragma unroll
        for (int i = t; i < 4 * DIM; i += 256) {
            int r = r0 + (i >> 7), c = i & 127;
            float a = b3[c];
#pragma unroll 4
            for (int k = 0; k < D_POS_IN; k++)
                a = fmaf(f3[r * D_POS_IN + k], W3[k * DIM + c], a);
            g_t3a[r * DIM + c] = a;
        }
        return;
    }
    const int* rows; int E, off, b0;
    if (b < H11)      { rows = r11; E = E11; off = CU11; b0 = 0; }
    else if (b < H22) { rows = r22; E = E22; off = CU22; b0 = H11; }
    else if (b < H33) { rows = r33; E = E33; off = CU33; b0 = H22; }
    else if (b < H01) { rows = r01; E = E01; off = CU01; b0 = H33; }
    else if (b < H02) { rows = r02; E = E02; off = CU02; b0 = H01; }
    else              { rows = r03; E = E03; off = CU03; b0 = H02; }
    int e0 = (b - b0) * 1024 + t;
#pragma unroll
    for (int j = 0; j < 4; j++) {
        int e = e0 + j * 256;
        if (e < E) atomicAdd(&g_cu[off + rows[e]], 1);
    }
}

__global__ void k_scan_all() {
    __shared__ int wsum[32];
    const int ns[6]  = {N_WORD, N_ENT, N_POS, N_DOC, N_DOC, N_DOC};
    const int cuo[6] = {CU11, CU22, CU33, CU01, CU02, CU03};
    const int rpo[6] = {RP11, RP22, RP33, RP01, RP02, RP03};
    int g = blockIdx.x;
    int n = ns[g];
    int* cnt = g_cu + cuo[g];
    int* rp  = g_rp + rpo[g];
    int tid = threadIdx.x;  // 1024
    int chunk = (n + 1023) >> 10;
    int base = tid * chunk;
    int end = base + chunk; if (end > n) end = n;
    int s = 0;
    for (int i = base; i < end && i >= base; i++) s += cnt[i];
    int lane = tid & 31, w = tid >> 5;
    int v = s;
#pragma unroll
    for (int o = 1; o < 32; o <<= 1) { int u = __shfl_up_sync(~0u, v, o); if (lane >= o) v += u; }
    if (lane == 31) wsum[w] = v;
    __syncthreads();
    if (w == 0) {
        int x = wsum[lane];
#pragma unroll
        for (int o = 1; o < 32; o <<= 1) { int u = __shfl_up_sync(~0u, x, o); if (lane >= o) x += u; }
        wsum[lane] = x;
    }
    __syncthreads();
    int excl = v - s + (w > 0 ? wsum[w - 1] : 0);
    int run = excl;
    for (int i = base; i < end && i >= base; i++) {
        int c = cnt[i];
        cnt[i] = run;
        rp[i] = run;
        run += c;
    }
    if (end == n || base >= n) rp[n] = run;
}

__global__ void k_scatter_all(const int* __restrict__ r11, const int* __restrict__ c11, const float* __restrict__ v11,
                              const int* __restrict__ r22, const int* __restrict__ c22, const float* __restrict__ v22,
                              const int* __restrict__ r33, const int* __restrict__ c33, const float* __restrict__ v33,
                              const int* __restrict__ r01, const int* __restrict__ c01, const float* __restrict__ v01,
                              const int* __restrict__ r02, const int* __restrict__ c02, const float* __restrict__ v02,
                              const int* __restrict__ r03, const int* __restrict__ c03, const float* __restrict__ v03) {
    int b = blockIdx.x, t = threadIdx.x;
    const int* rows; const int* cols; const float* vals; int E, cuoff, eoff, b0;
    if (b < H11)      { rows = r11; cols = c11; vals = v11; E = E11; cuoff = CU11; eoff = EO11; b0 = 0; }
    else if (b < H22) { rows = r22; cols = c22; vals = v22; E = E22; cuoff = CU22; eoff = EO22; b0 = H11; }
    else if (b < H33) { rows = r33; cols = c33; vals = v33; E = E33; cuoff = CU33; eoff = EO33; b0 = H22; }
    else if (b < H01) { rows = r01; cols = c01; vals = v01; E = E01; cuoff = CU01; eoff = EO01; b0 = H33; }
    else if (b < H02) { rows = r02; cols = c02; vals = v02; E = E02; cuoff = CU02; eoff = EO02; b0 = H01; }
    else              { rows = r03; cols = c03; vals = v03; E = E03; cuoff = CU03; eoff = EO03; b0 = H02; }
    int e0 = (b - b0) * 1024 + t;
#pragma unroll
    for (int j = 0; j < 4; j++) {
        int e = e0 + j * 256;
        if (e < E) {
            int slot = atomicAdd(&g_cu[cuoff + rows[e]], 1);
            g_ecv[eoff + slot] = make_int2(cols[e], __float_as_int(vals[e]));
        }
    }
}

// ---------------- spMM core: warp per row, lane holds 4 cols, edge-unrolled x4 ----------------
__device__ __forceinline__ float4 spmm_row_f4(const int* __restrict__ rp, const int2* __restrict__ ecv,
                                              const float4* __restrict__ x4, int row, int lane) {
    int s = rp[row], e = rp[row + 1];
    float4 acc = make_float4(0.f, 0.f, 0.f, 0.f);
    int i = s;
    for (; i + 3 < e; i += 4) {
        int2 e0 = ecv[i], e1 = ecv[i + 1], e2 = ecv[i + 2], e3 = ecv[i + 3];
        float v0 = __int_as_float(e0.y), v1 = __int_as_float(e1.y);
        float v2 = __int_as_float(e2.y), v3 = __int_as_float(e3.y);
        float4 a = x4[(size_t)e0.x * 32 + lane];
        float4 b = x4[(size_t)e1.x * 32 + lane];
        float4 c = x4[(size_t)e2.x * 32 + lane];
        float4 d = x4[(size_t)e3.x * 32 + lane];
        acc.x = fmaf(v0, a.x, fmaf(v1, b.x, fmaf(v2, c.x, fmaf(v3, d.x, acc.x))));
        acc.y = fmaf(v0, a.y, fmaf(v1, b.y, fmaf(v2, c.y, fmaf(v3, d.y, acc.y))));
        acc.z = fmaf(v0, a.z, fmaf(v1, b.z, fmaf(v2, c.z, fmaf(v3, d.z, acc.z))));
        acc.w = fmaf(v0, a.w, fmaf(v1, b.w, fmaf(v2, c.w, fmaf(v3, d.w, acc.w))));
    }
    for (; i < e; i++) {
        int2 e0 = ecv[i];
        float v0 = __int_as_float(e0.y);
        float4 a = x4[(size_t)e0.x * 32 + lane];
        acc.x = fmaf(v0, a.x, acc.x);
        acc.y = fmaf(v0, a.y, acc.y);
        acc.z = fmaf(v0, a.z, acc.z);
        acc.w = fmaf(v0, a.w, acc.w);
    }
    return acc;
}

__device__ __forceinline__ void store_relu_f4(float4 acc, float* __restrict__ y, int row, int lane) {
    ((float4*)y)[(size_t)row * 32 + lane] =
        make_float4(fmaxf(acc.x, 0.f), fmaxf(acc.y, 0.f), fmaxf(acc.z, 0.f), fmaxf(acc.w, 0.f));
}

__device__ __forceinline__ void store_norm_f4(float4 acc, float* __restrict__ y, int row, int lane) {
    float sq = acc.x * acc.x + acc.y * acc.y + acc.z * acc.z + acc.w * acc.w;
#pragma unroll
    for (int o = 16; o > 0; o >>= 1) sq += __shfl_xor_sync(~0u, sq, o);
    float s = 1.f / (sqrtf(sq) + 1e-9f);
    ((float4*)y)[(size_t)row * 32 + lane] = make_float4(acc.x * s, acc.y * s, acc.z * s, acc.w * s);
}

// ---------------- Stage A: spmm1(t1) + spmm1(t2) + t3 spmm1 ----------------
__global__ void k_stageA(const float* __restrict__ f1, const float* __restrict__ f2) {
    int b = blockIdx.x, t = threadIdx.x, lane = t & 31, w = t >> 5;
    if (b < 2500) {
        int row = b * 8 + w;
        float4 acc = spmm_row_f4(g_rp + RP11, g_ecv + EO11, (const float4*)f1, row, lane);
        store_relu_f4(acc, g_h1a, row, lane);
    } else if (b < 3750) {
        int row = (b - 2500) * 8 + w;
        float4 acc = spmm_row_f4(g_rp + RP22, g_ecv + EO22, (const float4*)f2, row, lane);
        store_relu_f4(acc, g_h2a, row, lane);
    } else {
        int row = (b - 3750) * 8 + w;
        if (row < N_POS) {
            float4 acc = spmm_row_f4(g_rp + RP33, g_ecv + EO33, (const float4*)g_t3a, row, lane);
            store_relu_f4(acc, g_t3b, row, lane);
        }
    }
}

// ---------------- FFMA2 GEMM, 64-row tiles: y = x @ W + b ----------------
__device__ __forceinline__ void gemm64_f2(const float* __restrict__ x, const float* __restrict__ W,
                                          const float* __restrict__ bias, float* __restrict__ y,
                                          int nrows, int r0, float* xs) {
    int t = threadIdx.x;
    const float4* x4 = (const float4*)x;
    float4* xs4 = (float4*)xs;
    for (int i = t; i < 64 * 32; i += 256) {
        int gr = r0 + (i >> 5);
        xs4[i] = (gr < nrows) ? x4[(size_t)gr * 32 + (i & 31)] : make_float4(0.f, 0.f, 0.f, 0.f);
    }
    __syncthreads();
    int cg = t & 31;   // cols 4cg .. 4cg+3
    int rg = t >> 5;   // rows rg*8 .. +8
    const float4* Wc = (const float4*)W;
    float4 b4 = ((const float4*)bias)[cg];
    ull acc[8][2];
#pragma unroll
    for (int r = 0; r < 8; r++) { acc[r][0] = pack2(b4.x, b4.y); acc[r][1] = pack2(b4.z, b4.w); }
    const float4* xr = xs4 + rg * 8 * 32;
    for (int k4 = 0; k4 < 32; k4++) {
        float4 xv[8];
#pragma unroll
        for (int r = 0; r < 8; r++) xv[r] = xr[r * 32 + k4];
#pragma unroll
        for (int kk = 0; kk < 4; kk++) {
            float4 wv = Wc[(k4 * 4 + kk) * 32 + cg];
            ull wp0 = pack2(wv.x, wv.y);
            ull wp1 = pack2(wv.z, wv.w);
#pragma unroll
            for (int r = 0; r < 8; r++) {
                float xsv = (kk == 0) ? xv[r].x : (kk == 1) ? xv[r].y : (kk == 2) ? xv[r].z : xv[r].w;
                ull xp = pack2(xsv, xsv);
                acc[r][0] = fma2(xp, wp0, acc[r][0]);
                acc[r][1] = fma2(xp, wp1, acc[r][1]);
            }
        }
    }
#pragma unroll
    for (int r = 0; r < 8; r++) {
        int gr = r0 + rg * 8 + r;
        if (gr < nrows) {
            float2 lo = unpack2(acc[r][0]);
            float2 hi = unpack2(acc[r][1]);
            ((float4*)y)[(size_t)gr * 32 + cg] = make_float4(lo.x, lo.y, hi.x, hi.y);
        }
    }
}

// ---------------- Stage B: gemm(t1) + gemm(t2) + t3 gemm2 ----------------
__global__ void k_stageB(const float* __restrict__ W1_2, const float* __restrict__ b1_2,
                         const float* __restrict__ W2_2, const float* __restrict__ b2_2,
                         const float* __restrict__ W3_2, const float* __restrict__ b3_2) {
    __shared__ float xs[64 * 128];
    int b = blockIdx.x;
    if (b < 313)      gemm64_f2(g_h1a, W1_2, b1_2, g_t1, N_WORD, b * 64, xs);
    else if (b < 470) gemm64_f2(g_h2a, W2_2, b2_2, g_t2, N_ENT, (b - 313) * 64, xs);
    else              gemm64_f2(g_t3b, W3_2, b3_2, g_t3a, N_POS, 0, xs);
}

// ---------------- Stage C: spmm2(t1) + spmm2(t2) + t3 spmm2 ----------------
__global__ void k_stageC() {
    int b = blockIdx.x, t = threadIdx.x, lane = t & 31, w = t >> 5;
    if (b < 2500) {
        int row = b * 8 + w;
        float4 acc = spmm_row_f4(g_rp + RP11, g_ecv + EO11, (const float4*)g_t1, row, lane);
        store_relu_f4(acc, g_h1, row, lane);
    } else if (b < 3750) {
        int row = (b - 2500) * 8 + w;
        float4 acc = spmm_row_f4(g_rp + RP22, g_ecv + EO22, (const float4*)g_t2, row, lane);
        store_relu_f4(acc, g_h2, row, lane);
    } else {
        int row = (b - 3750) * 8 + w;
        if (row < N_POS) {
            float4 acc = spmm_row_f4(g_rp + RP33, g_ecv + EO33, (const float4*)g_t3a, row, lane);
            store_relu_f4(acc, g_h3, row, lane);
        }
    }
}

// ---------------- Stage D (448 thr, 14 warps): out1 + out2 + out3 + cu re-zero ----------------
__global__ void k_stageD(const float* __restrict__ wemb, float* __restrict__ out) {
    int b = blockIdx.x, t = threadIdx.x, lane = t & 31, w = t >> 5;
    if (b < D_OUT1) {
        int row = b * 14 + w;
        if (row < N_DOC) {
            float4 acc = spmm_row_f4(g_rp + RP01, g_ecv + EO01, (const float4*)g_h1, row, lane);
            store_norm_f4(acc, out, row, lane);
        }
    } else if (b < D_OUT2) {
        __shared__ float red[14];
        int row = b - D_OUT1;
        const int* rp = g_rp + RP02;
        const int2* ecv = g_ecv + EO02;
        int s = rp[row], e = rp[row + 1];
        float acc0 = 0.f, acc1 = 0.f, acc2 = 0.f, acc3 = 0.f;
        if (t < DIM) {
            int i = s;
            for (; i + 3 < e; i += 4) {
                int2 e0 = ecv[i], e1 = ecv[i + 1], e2 = ecv[i + 2], e3 = ecv[i + 3];
                acc0 = fmaf(__int_as_float(e0.y), g_h2[(size_t)e0.x * DIM + t], acc0);
                acc1 = fmaf(__int_as_float(e1.y), g_h2[(size_t)e1.x * DIM + t], acc1);
                acc2 = fmaf(__int_as_float(e2.y), g_h2[(size_t)e2.x * DIM + t], acc2);
                acc3 = fmaf(__int_as_float(e3.y), g_h2[(size_t)e3.x * DIM + t], acc3);
            }
            for (; i < e; i++) {
                int2 e0 = ecv[i];
                acc0 = fmaf(__int_as_float(e0.y), g_h2[(size_t)e0.x * DIM + t], acc0);
            }
        } else if (t < DIM + D_WEMB) {
            int tc = t - DIM;
            int i = s;
            for (; i + 3 < e; i += 4) {
                int2 e0 = ecv[i], e1 = ecv[i + 1], e2 = ecv[i + 2], e3 = ecv[i + 3];
                acc0 = fmaf(__int_as_float(e0.y), wemb[(size_t)e0.x * D_WEMB + tc], acc0);
                acc1 = fmaf(__int_as_float(e1.y), wemb[(size_t)e1.x * D_WEMB + tc], acc1);
                acc2 = fmaf(__int_as_float(e2.y), wemb[(size_t)e2.x * D_WEMB + tc], acc2);
                acc3 = fmaf(__int_as_float(e3.y), wemb[(size_t)e3.x * D_WEMB + tc], acc3);
            }
            for (; i < e; i++) {
                int2 e0 = ecv[i];
                acc0 = fmaf(__int_as_float(e0.y), wemb[(size_t)e0.x * D_WEMB + tc], acc0);
            }
        }
        float acc = (acc0 + acc1) + (acc2 + acc3);
        float sq = acc * acc;
#pragma unroll
        for (int o = 16; o > 0; o >>= 1) sq += __shfl_xor_sync(~0u, sq, o);
        if (lane == 0) red[w] = sq;
        __syncthreads();
        if (t == 0) {
            float sum = 0.f;
#pragma unroll
            for (int i = 0; i < 14; i++) sum += red[i];
            red[0] = 1.f / (sqrtf(sum) + 1e-9f);
        }
        __syncthreads();
        float scale = red[0];
        if (t < DIM + D_WEMB)
            out[(size_t)N_DOC * DIM + (size_t)row * (DIM + D_WEMB) + t] = acc * scale;
    } else if (b < D_OUT3) {
        int row = (b - D_OUT2) * 14 + w;
        if (row < N_DOC) {
            float4 acc = spmm_row_f4(g_rp + RP03, g_ecv + EO03, (const float4*)g_h3, row, lane);
            float* out3 = out + (size_t)N_DOC * (DIM + DIM + D_WEMB);
            store_norm_f4(acc, out3, row, lane);
        }
    } else {
        // re-zero g_cu for the next graph replay (cursors are dead after scatter)
        int base = (b - D_OUT3) * 1024;
#pragma unroll
        for (int i = t; i < 1024; i += 448) {
            int idx = base + i;
            if (idx < CU_TOT) g_cu[idx] = 0;
        }
    }
}

// ---------------- host ----------------
extern "C" void kernel_launch(void* const* d_in, const int* in_sizes, int n_in,
                              void* d_out, int out_size) {
    const float* f1 = (const float*)d_in[0];
    const float* f2 = (const float*)d_in[1];
    const float* f3 = (const float*)d_in[2];
    const float* wemb = (const float*)d_in[3];
    const int* a11_r = (const int*)d_in[4];  const int* a11_c = (const int*)d_in[5];  const float* a11_v = (const float*)d_in[6];
    const int* a22_r = (const int*)d_in[7];  const int* a22_c = (const int*)d_in[8];  const float* a22_v = (const float*)d_in[9];
    const int* a33_r = (const int*)d_in[10]; const int* a33_c = (const int*)d_in[11]; const float* a33_v = (const float*)d_in[12];
    const int* a01_r = (const int*)d_in[13]; const int* a01_c = (const int*)d_in[14]; const float* a01_v = (const float*)d_in[15];
    const int* a02_r = (const int*)d_in[16]; const int* a02_c = (const int*)d_in[17]; const float* a02_v = (const float*)d_in[18];
    const int* a03_r = (const int*)d_in[19]; const int* a03_c = (const int*)d_in[20]; const float* a03_v = (const float*)d_in[21];
    const float* W3 = (const float*)d_in[22];   const float* b3 = (const float*)d_in[23];
    const float* W1_2 = (const float*)d_in[24]; const float* b1_2 = (const float*)d_in[25];
    const float* W2_2 = (const float*)d_in[26]; const float* b2_2 = (const float*)d_in[27];
    const float* W3_2 = (const float*)d_in[28]; const float* b3_2 = (const float*)d_in[29];

    float* out = (float*)d_out;

    // CSR build (g_cu zeroed by BSS init on first run, by stageD on every subsequent replay)
    k_hist_all<<<H03 + 15, 256>>>(a11_r, a22_r, a33_r, a01_r, a02_r, a03_r, f3, W3, b3);
    k_scan_all<<<6, 1024>>>();
    k_scatter_all<<<H03, 256>>>(a11_r, a11_c, a11_v, a22_r, a22_c, a22_v,
                                a33_r, a33_c, a33_v, a01_r, a01_c, a01_v,
                                a02_r, a02_c, a02_v, a03_r, a03_c, a03_v);

    // compute: 4 launches
    k_stageA<<<3758, 256>>>(f1, f2);
    k_stageB<<<471, 256>>>(W1_2, b1_2, W2_2, b2_2, W3_2, b3_2);
    k_stageC<<<3758, 256>>>();
    k_stageD<<<D_ZERO, 448>>>(wemb, out);
}

// round 8
// speedup vs baseline: 1.2470x; 1.0021x over previous
#include <cuda_runtime.h>
#include <math.h>

#define N_DOC 10000
#define N_WORD 20000
#define N_ENT 10000
#define N_POS 60
#define DIM 128
#define D_POS_IN 60
#define D_WEMB 300
#define E11 320000
#define E22 160000
#define E33 3600
#define E01 300000
#define E02 100000
#define E03 150000

typedef unsigned long long ull;

// merged offsets (compile time)
enum { CU11 = 0, CU22 = 20000, CU33 = 30000, CU01 = 30060, CU02 = 40060, CU03 = 50060, CU_TOT = 60060 };
enum { RP11 = 0, RP22 = 20001, RP33 = 30002, RP01 = 30063, RP02 = 40064, RP03 = 50065, RP_TOT = 60066 };
enum { EO11 = 0, EO22 = 320000, EO33 = 480000, EO01 = 483600, EO02 = 783600, EO03 = 883600, E_TOT = 1033600 };

// hist: 4 edges/thread (1024 edges/block), all six graphs
enum { H11 = 313, H22 = 470, H33 = 474, H01 = 767, H02 = 865, H03 = 1012 };
// node scatter (a11,a22,a33)
enum { SN11 = 313, SN22 = 470, SN33 = 474 };
// doc scatter fused in stageB: scatter blocks first, then gemm blocks
enum { SD01 = 293, SD02 = 391, SD03 = 538, BG1 = SD03 + 313, BG2 = BG1 + 157, B_TOT = BG2 + 1 };

// stageD layout: 448 threads (14 warps)
enum { D_OUT1 = 715, D_OUT2 = D_OUT1 + 10000, D_OUT3 = D_OUT2 + 715, D_ZERO = D_OUT3 + 59 };

// ---------------- scratch ----------------
__device__ int   g_cu[CU_TOT];
__device__ int   g_rp[RP_TOT];
__device__ int2  g_ecv[E_TOT];   // interleaved (col, val_bits)

__device__ float g_h1a[N_WORD * DIM];
__device__ float g_t1[N_WORD * DIM];
__device__ float g_h1[N_WORD * DIM];
__device__ float g_h2a[N_ENT * DIM];
__device__ float g_t2[N_ENT * DIM];
__device__ float g_h2[N_ENT * DIM];
__device__ float g_t3a[N_POS * DIM];
__device__ float g_t3b[N_POS * DIM];
__device__ float g_h3[N_POS * DIM];

// ---------------- packed fp32 helpers ----------------
__device__ __forceinline__ ull fma2(ull a, ull b, ull c) {
    ull d;
    asm("fma.rn.f32x2 %0, %1, %2, %3;" : "=l"(d) : "l"(a), "l"(b), "l"(c));
    return d;
}
__device__ __forceinline__ ull pack2(float lo, float hi) {
    ull d;
    asm("mov.b64 %0, {%1, %2};" : "=l"(d) : "f"(lo), "f"(hi));
    return d;
}
__device__ __forceinline__ float2 unpack2(ull v) {
    float2 r;
    asm("mov.b64 {%0, %1}, %2;" : "=f"(r.x), "=f"(r.y) : "l"(v));
    return r;
}

// ---------------- CSR build ----------------
// hist (all six graphs) + piggybacked dependency-free t3 gemm1: g_t3a = f3 @ W3 + b3
__global__ void k_hist_all(const int* __restrict__ r11, const int* __restrict__ r22,
                           const int* __restrict__ r33, const int* __restrict__ r01,
                           const int* __restrict__ r02, const int* __restrict__ r03,
                           const float* __restrict__ f3, const float* __restrict__ W3,
                           const float* __restrict__ b3) {
    int b = blockIdx.x, t = threadIdx.x;
    if (b >= H03) {
        int r0 = (b - H03) * 4;
#pragma unroll
        for (int i = t; i < 4 * DIM; i += 256) {
            int r = r0 + (i >> 7), c = i & 127;
            float a = b3[c];
#pragma unroll 4
            for (int k = 0; k < D_POS_IN; k++)
                a = fmaf(f3[r * D_POS_IN + k], W3[k * DIM + c], a);
            g_t3a[r * DIM + c] = a;
        }
        return;
    }
    const int* rows; int E, off, b0;
    if (b < H11)      { rows = r11; E = E11; off = CU11; b0 = 0; }
    else if (b < H22) { rows = r22; E = E22; off = CU22; b0 = H11; }
    else if (b < H33) { rows = r33; E = E33; off = CU33; b0 = H22; }
    else if (b < H01) { rows = r01; E = E01; off = CU01; b0 = H33; }
    else if (b < H02) { rows = r02; E = E02; off = CU02; b0 = H01; }
    else              { rows = r03; E = E03; off = CU03; b0 = H02; }
    int e0 = (b - b0) * 1024 + t;
#pragma unroll
    for (int j = 0; j < 4; j++) {
        int e = e0 + j * 256;
        if (e < E) atomicAdd(&g_cu[off + rows[e]], 1);
    }
}

__global__ void k_scan_all() {
    __shared__ int wsum[32];
    const int ns[6]  = {N_WORD, N_ENT, N_POS, N_DOC, N_DOC, N_DOC};
    const int cuo[6] = {CU11, CU22, CU33, CU01, CU02, CU03};
    const int rpo[6] = {RP11, RP22, RP33, RP01, RP02, RP03};
    int g = blockIdx.x;
    int n = ns[g];
    int* cnt = g_cu + cuo[g];
    int* rp  = g_rp + rpo[g];
    int tid = threadIdx.x;  // 1024
    int chunk = (n + 1023) >> 10;
    int base = tid * chunk;
    int end = base + chunk; if (end > n) end = n;
    int s = 0;
    for (int i = base; i < end && i >= base; i++) s += cnt[i];
    int lane = tid & 31, w = tid >> 5;
    int v = s;
#pragma unroll
    for (int o = 1; o < 32; o <<= 1) { int u = __shfl_up_sync(~0u, v, o); if (lane >= o) v += u; }
    if (lane == 31) wsum[w] = v;
    __syncthreads();
    if (w == 0) {
        int x = wsum[lane];
#pragma unroll
        for (int o = 1; o < 32; o <<= 1) { int u = __shfl_up_sync(~0u, x, o); if (lane >= o) x += u; }
        wsum[lane] = x;
    }
    __syncthreads();
    int excl = v - s + (w > 0 ? wsum[w - 1] : 0);
    int run = excl;
    for (int i = base; i < end && i >= base; i++) {
        int c = cnt[i];
        cnt[i] = run;
        rp[i] = run;
        run += c;
    }
    if (end == n || base >= n) rp[n] = run;
}

__device__ __forceinline__ void scatter_range(const int* __restrict__ rows, const int* __restrict__ cols,
                                              const float* __restrict__ vals, int E, int cuoff, int eoff,
                                              int rel_b, int t) {
    int e0 = rel_b * 1024 + t;
#pragma unroll
    for (int j = 0; j < 4; j++) {
        int e = e0 + j * 256;
        if (e < E) {
            int slot = atomicAdd(&g_cu[cuoff + rows[e]], 1);
            g_ecv[eoff + slot] = make_int2(cols[e], __float_as_int(vals[e]));
        }
    }
}

// node graphs only (a11, a22, a33)
__global__ void k_scatter_nodes(const int* __restrict__ r11, const int* __restrict__ c11, const float* __restrict__ v11,
                                const int* __restrict__ r22, const int* __restrict__ c22, const float* __restrict__ v22,
                                const int* __restrict__ r33, const int* __restrict__ c33, const float* __restrict__ v33) {
    int b = blockIdx.x, t = threadIdx.x;
    if (b < SN11)      scatter_range(r11, c11, v11, E11, CU11, EO11, b, t);
    else if (b < SN22) scatter_range(r22, c22, v22, E22, CU22, EO22, b - SN11, t);
    else               scatter_range(r33, c33, v33, E33, CU33, EO33, b - SN22, t);
}

// ---------------- spMM core: warp per row, lane holds 4 cols, edge-unrolled x4 ----------------
__device__ __forceinline__ float4 spmm_row_f4(const int* __restrict__ rp, const int2* __restrict__ ecv,
                                              const float4* __restrict__ x4, int row, int lane) {
    int s = rp[row], e = rp[row + 1];
    float4 acc = make_float4(0.f, 0.f, 0.f, 0.f);
    int i = s;
    for (; i + 3 < e; i += 4) {
        int2 e0 = ecv[i], e1 = ecv[i + 1], e2 = ecv[i + 2], e3 = ecv[i + 3];
        float v0 = __int_as_float(e0.y), v1 = __int_as_float(e1.y);
        float v2 = __int_as_float(e2.y), v3 = __int_as_float(e3.y);
        float4 a = x4[(size_t)e0.x * 32 + lane];
        float4 b = x4[(size_t)e1.x * 32 + lane];
        float4 c = x4[(size_t)e2.x * 32 + lane];
        float4 d = x4[(size_t)e3.x * 32 + lane];
        acc.x = fmaf(v0, a.x, fmaf(v1, b.x, fmaf(v2, c.x, fmaf(v3, d.x, acc.x))));
        acc.y = fmaf(v0, a.y, fmaf(v1, b.y, fmaf(v2, c.y, fmaf(v3, d.y, acc.y))));
        acc.z = fmaf(v0, a.z, fmaf(v1, b.z, fmaf(v2, c.z, fmaf(v3, d.z, acc.z))));
        acc.w = fmaf(v0, a.w, fmaf(v1, b.w, fmaf(v2, c.w, fmaf(v3, d.w, acc.w))));
    }
    for (; i < e; i++) {
        int2 e0 = ecv[i];
        float v0 = __int_as_float(e0.y);
        float4 a = x4[(size_t)e0.x * 32 + lane];
        acc.x = fmaf(v0, a.x, acc.x);
        acc.y = fmaf(v0, a.y, acc.y);
        acc.z = fmaf(v0, a.z, acc.z);
        acc.w = fmaf(v0, a.w, acc.w);
    }
    return acc;
}

__device__ __forceinline__ void store_relu_f4(float4 acc, float* __restrict__ y, int row, int lane) {
    ((float4*)y)[(size_t)row * 32 + lane] =
        make_float4(fmaxf(acc.x, 0.f), fmaxf(acc.y, 0.f), fmaxf(acc.z, 0.f), fmaxf(acc.w, 0.f));
}

__device__ __forceinline__ void store_norm_f4(float4 acc, float* __restrict__ y, int row, int lane) {
    float sq = acc.x * acc.x + acc.y * acc.y + acc.z * acc.z + acc.w * acc.w;
#pragma unroll
    for (int o = 16; o > 0; o >>= 1) sq += __shfl_xor_sync(~0u, sq, o);
    float s = 1.f / (sqrtf(sq) + 1e-9f);
    ((float4*)y)[(size_t)row * 32 + lane] = make_float4(acc.x * s, acc.y * s, acc.z * s, acc.w * s);
}

// ---------------- Stage A: spmm1(t1) + spmm1(t2) + t3 spmm1 ----------------
__global__ void k_stageA(const float* __restrict__ f1, const float* __restrict__ f2) {
    int b = blockIdx.x, t = threadIdx.x, lane = t & 31, w = t >> 5;
    if (b < 2500) {
        int row = b * 8 + w;
        float4 acc = spmm_row_f4(g_rp + RP11, g_ecv + EO11, (const float4*)f1, row, lane);
        store_relu_f4(acc, g_h1a, row, lane);
    } else if (b < 3750) {
        int row = (b - 2500) * 8 + w;
        float4 acc = spmm_row_f4(g_rp + RP22, g_ecv + EO22, (const float4*)f2, row, lane);
        store_relu_f4(acc, g_h2a, row, lane);
    } else {
        int row = (b - 3750) * 8 + w;
        if (row < N_POS) {
            float4 acc = spmm_row_f4(g_rp + RP33, g_ecv + EO33, (const float4*)g_t3a, row, lane);
            store_relu_f4(acc, g_t3b, row, lane);
        }
    }
}

// ---------------- FFMA2 GEMM, 64-row tiles: y = x @ W + b ----------------
__device__ __forceinline__ void gemm64_f2(const float* __restrict__ x, const float* __restrict__ W,
                                          const float* __restrict__ bias, float* __restrict__ y,
                                          int nrows, int r0, float* xs) {
    int t = threadIdx.x;
    const float4* x4 = (const float4*)x;
    float4* xs4 = (float4*)xs;
    for (int i = t; i < 64 * 32; i += 256) {
        int gr = r0 + (i >> 5);
        xs4[i] = (gr < nrows) ? x4[(size_t)gr * 32 + (i & 31)] : make_float4(0.f, 0.f, 0.f, 0.f);
    }
    __syncthreads();
    int cg = t & 31;   // cols 4cg .. 4cg+3
    int rg = t >> 5;   // rows rg*8 .. +8
    const float4* Wc = (const float4*)W;
    float4 b4 = ((const float4*)bias)[cg];
    ull acc[8][2];
#pragma unroll
    for (int r = 0; r < 8; r++) { acc[r][0] = pack2(b4.x, b4.y); acc[r][1] = pack2(b4.z, b4.w); }
    const float4* xr = xs4 + rg * 8 * 32;
    for (int k4 = 0; k4 < 32; k4++) {
        float4 xv[8];
#pragma unroll
        for (int r = 0; r < 8; r++) xv[r] = xr[r * 32 + k4];
#pragma unroll
        for (int kk = 0; kk < 4; kk++) {
            float4 wv = Wc[(k4 * 4 + kk) * 32 + cg];
            ull wp0 = pack2(wv.x, wv.y);
            ull wp1 = pack2(wv.z, wv.w);
#pragma unroll
            for (int r = 0; r < 8; r++) {
                float xsv = (kk == 0) ? xv[r].x : (kk == 1) ? xv[r].y : (kk == 2) ? xv[r].z : xv[r].w;
                ull xp = pack2(xsv, xsv);
                acc[r][0] = fma2(xp, wp0, acc[r][0]);
                acc[r][1] = fma2(xp, wp1, acc[r][1]);
            }
        }
    }
#pragma unroll
    for (int r = 0; r < 8; r++) {
        int gr = r0 + rg * 8 + r;
        if (gr < nrows) {
            float2 lo = unpack2(acc[r][0]);
            float2 hi = unpack2(acc[r][1]);
            ((float4*)y)[(size_t)gr * 32 + cg] = make_float4(lo.x, lo.y, hi.x, hi.y);
        }
    }
}

// ---------------- Stage B: doc scatter (mem-bound) + gemm t1/t2/t3 (fma-bound), overlapped ----------------
__global__ void k_stageB(const int* __restrict__ r01, const int* __restrict__ c01, const float* __restrict__ v01,
                         const int* __restrict__ r02, const int* __restrict__ c02, const float* __restrict__ v02,
                         const int* __restrict__ r03, const int* __restrict__ c03, const float* __restrict__ v03,
                         const float* __restrict__ W1_2, const float* __restrict__ b1_2,
                         const float* __restrict__ W2_2, const float* __restrict__ b2_2,
                         const float* __restrict__ W3_2, const float* __restrict__ b3_2) {
    __shared__ float xs[64 * 128];
    int b = blockIdx.x, t = threadIdx.x;
    if (b < SD01)      { scatter_range(r01, c01, v01, E01, CU01, EO01, b, t); return; }
    else if (b < SD02) { scatter_range(r02, c02, v02, E02, CU02, EO02, b - SD01, t); return; }
    else if (b < SD03) { scatter_range(r03, c03, v03, E03, CU03, EO03, b - SD02, t); return; }
    else if (b < BG1)  gemm64_f2(g_h1a, W1_2, b1_2, g_t1, N_WORD, (b - SD03) * 64, xs);
    else if (b < BG2)  gemm64_f2(g_h2a, W2_2, b2_2, g_t2, N_ENT, (b - BG1) * 64, xs);
    else               gemm64_f2(g_t3b, W3_2, b3_2, g_t3a, N_POS, 0, xs);
}

// ---------------- Stage C: spmm2(t1) + spmm2(t2) + t3 spmm2 ----------------
__global__ void k_stageC() {
    int b = blockIdx.x, t = threadIdx.x, lane = t & 31, w = t >> 5;
    if (b < 2500) {
        int row = b * 8 + w;
        float4 acc = spmm_row_f4(g_rp + RP11, g_ecv + EO11, (const float4*)g_t1, row, lane);
        store_relu_f4(acc, g_h1, row, lane);
    } else if (b < 3750) {
        int row = (b - 2500) * 8 + w;
        float4 acc = spmm_row_f4(g_rp + RP22, g_ecv + EO22, (const float4*)g_t2, row, lane);
        store_relu_f4(acc, g_h2, row, lane);
    } else {
        int row = (b - 3750) * 8 + w;
        if (row < N_POS) {
            float4 acc = spmm_row_f4(g_rp + RP33, g_ecv + EO33, (const float4*)g_t3a, row, lane);
            store_relu_f4(acc, g_h3, row, lane);
        }
    }
}

// ---------------- Stage D (448 thr, 14 warps): out1 + out2 + out3 + cu re-zero ----------------
__global__ void k_stageD(const float* __restrict__ wemb, float* __restrict__ out) {
    int b = blockIdx.x, t = threadIdx.x, lane = t & 31, w = t >> 5;
    if (b < D_OUT1) {
        int row = b * 14 + w;
        if (row < N_DOC) {
            float4 acc = spmm_row_f4(g_rp + RP01, g_ecv + EO01, (const float4*)g_h1, row, lane);
            store_norm_f4(acc, out, row, lane);
        }
    } else if (b < D_OUT2) {
        __shared__ float red[14];
        int row = b - D_OUT1;
        const int* rp = g_rp + RP02;
        const int2* ecv = g_ecv + EO02;
        int s = rp[row], e = rp[row + 1];
        float acc0 = 0.f, acc1 = 0.f, acc2 = 0.f, acc3 = 0.f;
        if (t < DIM) {
            int i = s;
            for (; i + 3 < e; i += 4) {
                int2 e0 = ecv[i], e1 = ecv[i + 1], e2 = ecv[i + 2], e3 = ecv[i + 3];
                acc0 = fmaf(__int_as_float(e0.y), g_h2[(size_t)e0.x * DIM + t], acc0);
                acc1 = fmaf(__int_as_float(e1.y), g_h2[(size_t)e1.x * DIM + t], acc1);
                acc2 = fmaf(__int_as_float(e2.y), g_h2[(size_t)e2.x * DIM + t], acc2);
                acc3 = fmaf(__int_as_float(e3.y), g_h2[(size_t)e3.x * DIM + t], acc3);
            }
            for (; i < e; i++) {
                int2 e0 = ecv[i];
                acc0 = fmaf(__int_as_float(e0.y), g_h2[(size_t)e0.x * DIM + t], acc0);
            }
        } else if (t < DIM + D_WEMB) {
            int tc = t - DIM;
            int i = s;
            for (; i + 3 < e; i += 4) {
                int2 e0 = ecv[i], e1 = ecv[i + 1], e2 = ecv[i + 2], e3 = ecv[i + 3];
                acc0 = fmaf(__int_as_float(e0.y), wemb[(size_t)e0.x * D_WEMB + tc], acc0);
                acc1 = fmaf(__int_as_float(e1.y), wemb[(size_t)e1.x * D_WEMB + tc], acc1);
                acc2 = fmaf(__int_as_float(e2.y), wemb[(size_t)e2.x * D_WEMB + tc], acc2);
                acc3 = fmaf(__int_as_float(e3.y), wemb[(size_t)e3.x * D_WEMB + tc], acc3);
            }
            for (; i < e; i++) {
                int2 e0 = ecv[i];
                acc0 = fmaf(__int_as_float(e0.y), wemb[(size_t)e0.x * D_WEMB + tc], acc0);
            }
        }
        float acc = (acc0 + acc1) + (acc2 + acc3);
        float sq = acc * acc;
#pragma unroll
        for (int o = 16; o > 0; o >>= 1) sq += __shfl_xor_sync(~0u, sq, o);
        if (lane == 0) red[w] = sq;
        __syncthreads();
        if (t == 0) {
            float sum = 0.f;
#pragma unroll
            for (int i = 0; i < 14; i++) sum += red[i];
            red[0] = 1.f / (sqrtf(sum) + 1e-9f);
        }
        __syncthreads();
        float scale = red[0];
        if (t < DIM + D_WEMB)
            out[(size_t)N_DOC * DIM + (size_t)row * (DIM + D_WEMB) + t] = acc * scale;
    } else if (b < D_OUT3) {
        int row = (b - D_OUT2) * 14 + w;
        if (row < N_DOC) {
            float4 acc = spmm_row_f4(g_rp + RP03, g_ecv + EO03, (const float4*)g_h3, row, lane);
            float* out3 = out + (size_t)N_DOC * (DIM + DIM + D_WEMB);
            store_norm_f4(acc, out3, row, lane);
        }
    } else {
        // re-zero g_cu for the next graph replay (cursors are dead after both scatters)
        int base = (b - D_OUT3) * 1024;
#pragma unroll
        for (int i = t; i < 1024; i += 448) {
            int idx = base + i;
            if (idx < CU_TOT) g_cu[idx] = 0;
        }
    }
}

// ---------------- host ----------------
extern "C" void kernel_launch(void* const* d_in, const int* in_sizes, int n_in,
                              void* d_out, int out_size) {
    const float* f1 = (const float*)d_in[0];
    const float* f2 = (const float*)d_in[1];
    const float* f3 = (const float*)d_in[2];
    const float* wemb = (const float*)d_in[3];
    const int* a11_r = (const int*)d_in[4];  const int* a11_c = (const int*)d_in[5];  const float* a11_v = (const float*)d_in[6];
    const int* a22_r = (const int*)d_in[7];  const int* a22_c = (const int*)d_in[8];  const float* a22_v = (const float*)d_in[9];
    const int* a33_r = (const int*)d_in[10]; const int* a33_c = (const int*)d_in[11]; const float* a33_v = (const float*)d_in[12];
    const int* a01_r = (const int*)d_in[13]; const int* a01_c = (const int*)d_in[14]; const float* a01_v = (const float*)d_in[15];
    const int* a02_r = (const int*)d_in[16]; const int* a02_c = (const int*)d_in[17]; const float* a02_v = (const float*)d_in[18];
    const int* a03_r = (const int*)d_in[19]; const int* a03_c = (const int*)d_in[20]; const float* a03_v = (const float*)d_in[21];
    const float* W3 = (const float*)d_in[22];   const float* b3 = (const float*)d_in[23];
    const float* W1_2 = (const float*)d_in[24]; const float* b1_2 = (const float*)d_in[25];
    const float* W2_2 = (const float*)d_in[26]; const float* b2_2 = (const float*)d_in[27];
    const float* W3_2 = (const float*)d_in[28]; const float* b3_2 = (const float*)d_in[29];

    float* out = (float*)d_out;

    // CSR build: doc scatter deferred into stageB (overlaps FMA-bound gemm)
    k_hist_all<<<H03 + 15, 256>>>(a11_r, a22_r, a33_r, a01_r, a02_r, a03_r, f3, W3, b3);
    k_scan_all<<<6, 1024>>>();
    k_scatter_nodes<<<SN33, 256>>>(a11_r, a11_c, a11_v, a22_r, a22_c, a22_v, a33_r, a33_c, a33_v);

    // compute
    k_stageA<<<3758, 256>>>(f1, f2);
    k_stageB<<<B_TOT, 256>>>(a01_r, a01_c, a01_v, a02_r, a02_c, a02_v, a03_r, a03_c, a03_v,
                             W1_2, b1_2, W2_2, b2_2, W3_2, b3_2);
    k_stageC<<<3758, 256>>>();
    k_stageD<<<D_ZERO, 448>>>(wemb, out);
}